// round 6
// baseline (speedup 1.0000x reference)
#include <cuda_runtime.h>
#include <cstdint>

// Problem constants
#define B 8
#define N 4096
#define C 1024
#define H 16
#define D 64
#define SCALE 0.125f

typedef unsigned long long ull;

// Scratch (no cudaMalloc allowed)
__device__ float g_k[B * C];       // [b][h*D+d]
__device__ float g_v[B * C];
__device__ float g_u[B * H * C];   // [b][h][c]  folded Wq*k
__device__ float g_M[B * H * C];   // [b][h][c]  folded Wp*v

// Packed fp32x2 helpers (sm_103a)
#define FMA2(acc, a, bb) asm("fma.rn.f32x2 %0, %1, %2, %0;" : "+l"(acc) : "l"(a), "l"(bb))
#define ADD2(d, a, bb)   asm("add.rn.f32x2 %0, %1, %2;"     : "=l"(d)   : "l"(a), "l"(bb))

// Volatile loads: ptxas cannot sink these -> guaranteed front-batched MLP.
#define LDGV4(dst, ptr)                                                     \
  asm volatile("ld.global.nc.v4.f32 {%0,%1,%2,%3}, [%4];"                   \
               : "=f"(dst.x), "=f"(dst.y), "=f"(dst.z), "=f"(dst.w)         \
               : "l"(ptr))
#define LDGF(dst, ptr) \
  asm volatile("ld.global.nc.f32 %0, [%1];" : "=f"(dst) : "l"(ptr))

#define CPASYNC16(smem_u32, gptr)                                           \
  asm volatile("cp.async.cg.shared.global [%0], [%1], 16;" ::"r"(smem_u32), \
               "l"(gptr))
#define COMMIT() asm volatile("cp.async.commit_group;" ::: "memory")
#define WAITG(n) asm volatile("cp.async.wait_group %0;" ::"n"(n) : "memory")

// ---------------------------------------------------------------------------
// P1: k = emb @ Wk.T, v = emb @ Wv.T.   (unchanged — protected win)
// ---------------------------------------------------------------------------
__global__ void __launch_bounds__(128) precompute_kv(
    const float* __restrict__ emb, const float* __restrict__ Wk,
    const float* __restrict__ Wv) {
  int gw = (blockIdx.x * 128 + threadIdx.x) >> 5;  // 0..4095
  int lane = threadIdx.x & 31;
  int sel = gw >> 11;
  int rem = gw & 2047;
  int j = rem >> 1;
  int bh = (rem & 1) * 4;
  const float* W = sel ? Wv : Wk;
  float* dst = sel ? g_v : g_k;
  const float4* w4 = reinterpret_cast<const float4*>(W + j * C);
  const float4* e4 = reinterpret_cast<const float4*>(emb);

  float4 wv[8];
#pragma unroll
  for (int i = 0; i < 8; i++) LDGV4(wv[i], w4 + lane + 32 * i);

  float acc[4];
#pragma unroll
  for (int b = 0; b < 4; b++) acc[b] = 0.f;
#pragma unroll
  for (int b = 0; b < 4; b++) {
    float4 e[8];
#pragma unroll
    for (int i = 0; i < 8; i++) e[i] = e4[(bh + b) * 256 + lane + 32 * i];
#pragma unroll
    for (int i = 0; i < 8; i++)
      acc[b] += wv[i].x * e[i].x + wv[i].y * e[i].y + wv[i].z * e[i].z +
                wv[i].w * e[i].w;
  }
#pragma unroll
  for (int b = 0; b < 4; b++)
    for (int s = 16; s; s >>= 1) acc[b] += __shfl_xor_sync(0xffffffffu, acc[b], s);
  if (lane == 0) {
#pragma unroll
    for (int b = 0; b < 4; b++) dst[(bh + b) * C + j] = acc[b];
  }
}

// ---------------------------------------------------------------------------
// P2: u/M fold.  grid (4,16,2): batch-group of 4 -> Wq/Wp read only 2x (16MB).
// ---------------------------------------------------------------------------
__global__ void __launch_bounds__(256) precompute_uM(
    const float* __restrict__ Wq, const float* __restrict__ Wp) {
  __shared__ float kk[4][D];
  __shared__ float vv[4][D];
  int h = blockIdx.y;
  int bg = blockIdx.z * 4;
  int c = blockIdx.x * 256 + threadIdx.x;
  {
    int b = threadIdx.x >> 6, d = threadIdx.x & 63;
    kk[b][d] = g_k[(bg + b) * C + h * D + d];
    vv[b][d] = g_v[(bg + b) * C + h * D + d];
  }
  __syncthreads();

  float acc[4];
#pragma unroll
  for (int b = 0; b < 4; b++) acc[b] = 0.f;
#pragma unroll
  for (int d0 = 0; d0 < D; d0 += 16) {
    float wq[16];
#pragma unroll
    for (int jj = 0; jj < 16; jj++) LDGF(wq[jj], Wq + (h * D + d0 + jj) * C + c);
#pragma unroll
    for (int jj = 0; jj < 16; jj++)
#pragma unroll
      for (int b = 0; b < 4; b++) acc[b] += wq[jj] * kk[b][d0 + jj];
  }
#pragma unroll
  for (int b = 0; b < 4; b++) g_u[((bg + b) * H + h) * C + c] = acc[b];

  float acc2[4];
#pragma unroll
  for (int b = 0; b < 4; b++) acc2[b] = 0.f;
  const float4* wp4 = reinterpret_cast<const float4*>(Wp + c * C + h * D);
#pragma unroll
  for (int i0 = 0; i0 < 16; i0 += 8) {
    float4 wp[8];
#pragma unroll
    for (int i = 0; i < 8; i++) LDGV4(wp[i], wp4 + i0 + i);
#pragma unroll
    for (int i = 0; i < 8; i++) {
      int d = (i0 + i) * 4;
#pragma unroll
      for (int b = 0; b < 4; b++)
        acc2[b] += wp[i].x * vv[b][d] + wp[i].y * vv[b][d + 1] +
                   wp[i].z * vv[b][d + 2] + wp[i].w * vv[b][d + 3];
    }
  }
#pragma unroll
  for (int b = 0; b < 4; b++) g_M[((bg + b) * H + h) * C + c] = acc2[b];
}

// ---------------------------------------------------------------------------
// MAIN: persistent row-group streaming pipeline.
// 148 blocks x 512 threads. Groups of 8 full-width rows (32KB), 4 rotating
// cp.async buffers keyed by g&3 EVERYWHERE (R5 bug: prologue used fixed
// buffers 0,1,2 while the consumer read g&3; broken for gs%4 != 0).
// One commit per iteration -> wait_group 3 = continuous 3-deep prefetch.
// ---------------------------------------------------------------------------
#define GROUPS (B * N / 8)   // 4096
#define NBLK 148
#define GSTR 1028            // floats per staged row (1024 + pad 4)
#define GF (8 * GSTR)        // floats per group buffer = 8224
#define NBUF 4
#define U_FLOATS (H * C)     // 16384
#define PART_STRIDE 20
#define PART_FLOATS (16 * 8 * PART_STRIDE)  // 2560
#define SMEM_FLOATS (U_FLOATS + NBUF * GF + PART_FLOATS + 8 * H * 2)

__global__ void __launch_bounds__(512, 1) gate_main(
    const float* __restrict__ fea, const float* __restrict__ bp,
    float* __restrict__ out) {
  extern __shared__ __align__(16) float sm[];
  float* u_s = sm;                                   // [h][c] 16384
  float* bufs = sm + U_FLOATS;                       // 4 x 8224
  float* part = bufs + NBUF * GF;                    // [w][r][20]
  ull* attn_d = reinterpret_cast<ull*>(part + PART_FLOATS);  // [r][h]

  const int t = threadIdx.x;
  const int w = t >> 5;
  const int l = t & 31;
  const int c0 = t * 2;            // phase-2 column pair
  const int r1 = t & 7;            // phase-1 row
  const int seg = t >> 3;          // phase-1 16-col segment (0..63)

  const int gs = (int)(((long)blockIdx.x * GROUPS) / NBLK);
  const int ge = (int)(((long)(blockIdx.x + 1) * GROUPS) / NBLK);

  // issue one full 8x1024 group (2048 x 16B) into buffer `buf`
#define ISSUE_G(g, buf)                                                     \
  {                                                                         \
    const float* srcb = fea + (size_t)(g) * 8192;                           \
    float* db = bufs + (buf) * GF;                                          \
    _Pragma("unroll") for (int i = 0; i < 4; i++) {                         \
      int idx = t + 512 * i;                                                \
      int r = idx >> 8;                                                     \
      int c4 = idx & 255;                                                   \
      unsigned ds =                                                         \
          (unsigned)__cvta_generic_to_shared(db + r * GSTR + c4 * 4);       \
      CPASYNC16(ds, srcb + r * 1024 + c4 * 4);                              \
    }                                                                       \
  }

  // prologue: 3 groups in flight, buffers keyed by group index (FIX)
  ISSUE_G(gs, gs & 3); COMMIT();
  ISSUE_G(gs + 1, (gs + 1) & 3); COMMIT();
  ISSUE_G(gs + 2, (gs + 2) & 3); COMMIT();

  ull bpv = *reinterpret_cast<const ull*>(bp + c0);
  ull M2[H];
  int cur_b = -1;

  for (int g = gs; g < ge; ++g) {
    const int buf = g & 3;
    // exactly one commit per iteration (possibly empty) keeps the count fixed
    if (g + 3 < ge) { ISSUE_G(g + 3, (g + 3) & 3); }
    COMMIT();

    const int b = g >> 9;
    if (b != cur_b) {
      cur_b = b;
      WAITG(0);
      // u[b] -> smem
      const float4* gu4 = reinterpret_cast<const float4*>(g_u + b * U_FLOATS);
#pragma unroll
      for (int i = 0; i < 8; i++) {
        int idx = t + 512 * i;
        unsigned ds = (unsigned)__cvta_generic_to_shared(u_s + idx * 4);
        CPASYNC16(ds, gu4 + idx);
      }
      COMMIT();
      WAITG(0);
      __syncthreads();
#pragma unroll
      for (int h = 0; h < H; h++)
        M2[h] = *reinterpret_cast<const ull*>(g_M + (b * H + h) * C + c0);
    } else {
      WAITG(3);
      __syncthreads();
    }

    const float* fb = bufs + buf * GF;

    // ---- Phase 1: scores.  thread = (row r1, 16-col segment seg) ----
    ull acc[H];
#pragma unroll
    for (int h = 0; h < H; h++) acc[h] = 0ull;
    const float* fp = fb + r1 * GSTR + seg * 16;
    const float* up = u_s + seg * 16;
#pragma unroll
    for (int j = 0; j < 4; j++) {
      ulonglong2 f = *reinterpret_cast<const ulonglong2*>(fp + j * 4);
#pragma unroll
      for (int h = 0; h < H; h++) {
        ulonglong2 uu = *reinterpret_cast<const ulonglong2*>(up + h * C + j * 4);
        FMA2(acc[h], f.x, uu.x);
        FMA2(acc[h], f.y, uu.y);
      }
    }
    // fold packed halves, reduce the warp's 4 segments (lanes l, l^8, l^16,
    // l^24 share the same row r1)
    float s[H];
#pragma unroll
    for (int h = 0; h < H; h++) {
      float lo, hi;
      asm("mov.b64 {%0,%1}, %2;" : "=f"(lo), "=f"(hi) : "l"(acc[h]));
      s[h] = lo + hi;
      s[h] += __shfl_xor_sync(0xffffffffu, s[h], 8);
      s[h] += __shfl_xor_sync(0xffffffffu, s[h], 16);
    }
    if (l < 8) {
      float* pp = part + (w * 8 + l) * PART_STRIDE;
#pragma unroll
      for (int h4 = 0; h4 < 4; h4++) {
        float4 v4 = make_float4(s[h4 * 4], s[h4 * 4 + 1], s[h4 * 4 + 2],
                                s[h4 * 4 + 3]);
        *reinterpret_cast<float4*>(pp + h4 * 4) = v4;
      }
    }
    __syncthreads();

    // reduce over 16 warps + sigmoid -> duplicated f32x2 attn
    if (t < 128) {
      int rr = t >> 4, h = t & 15;
      float sum = 0.f;
#pragma unroll
      for (int ww = 0; ww < 16; ww++)
        sum += part[(ww * 8 + rr) * PART_STRIDE + h];
      float a = 1.f / (1.f + __expf(-sum * SCALE));
      ull ad;
      asm("mov.b64 %0, {%1,%1};" : "=l"(ad) : "f"(a));
      attn_d[rr * H + h] = ad;
    }
    __syncthreads();

    // ---- Phase 2: out = fea(smem) + bp + attn @ M2.  thread = col pair ----
    float* ob = out + (size_t)g * 8192 + c0;
#pragma unroll
    for (int rr = 0; rr < 8; rr++) {
      ull f = *reinterpret_cast<const ull*>(fb + rr * GSTR + c0);
      ull o;
      ADD2(o, f, bpv);
      const ull* ar = attn_d + rr * H;
#pragma unroll
      for (int hg = 0; hg < 8; hg++) {
        ulonglong2 a2 = *reinterpret_cast<const ulonglong2*>(ar + hg * 2);
        FMA2(o, a2.x, M2[hg * 2]);
        FMA2(o, a2.y, M2[hg * 2 + 1]);
      }
      *reinterpret_cast<ull*>(ob + rr * 1024) = o;
    }
    __syncthreads();  // release buffer `buf` for the prefetch 4 iters ahead
  }
}

// ---------------------------------------------------------------------------
extern "C" void kernel_launch(void* const* d_in, const int* in_sizes, int n_in,
                              void* d_out, int out_size) {
  const float* fea = (const float*)d_in[0];
  const float* emb = (const float*)d_in[1];
  const float* Wq  = (const float*)d_in[2];
  const float* Wk  = (const float*)d_in[3];
  const float* Wv  = (const float*)d_in[4];
  const float* Wp  = (const float*)d_in[5];
  const float* bp  = (const float*)d_in[6];
  float* out = (float*)d_out;

  const int smem_main = SMEM_FLOATS * 4;  // ~208 KB
  cudaFuncSetAttribute(gate_main, cudaFuncAttributeMaxDynamicSharedMemorySize,
                       smem_main);

  precompute_kv<<<1024, 128>>>(emb, Wk, Wv);
  precompute_uM<<<dim3(4, H, 2), 256>>>(Wq, Wp);
  gate_main<<<NBLK, 512, smem_main>>>(fea, bp, out);
}

// round 7
// speedup vs baseline: 1.0399x; 1.0399x over previous
#include <cuda_runtime.h>
#include <cstdint>

// Problem constants
#define B 8
#define N 4096
#define C 1024
#define H 16
#define D 64
#define SCALE 0.125f

typedef unsigned long long ull;

// Scratch (no cudaMalloc allowed)
__device__ float g_k[B * C];        // [b][h*D+d]
__device__ float g_v[B * C];
__device__ float g_u[B * H * C];    // [b][h][c]  folded Wq*k
__device__ float g_M[B * H * C];    // [b][h][c]  folded Wp*v
__device__ ull g_attnd[B * N * H];  // duplicated f32x2 sigmoid gates, 4MB

// Packed fp32x2 helpers (sm_103a)
#define FMA2(acc, a, bb) asm("fma.rn.f32x2 %0, %1, %2, %0;" : "+l"(acc) : "l"(a), "l"(bb))
#define ADD2(d, a, bb)   asm("add.rn.f32x2 %0, %1, %2;"     : "=l"(d)   : "l"(a), "l"(bb))

// Volatile loads: ptxas cannot sink these -> guaranteed front-batched MLP.
#define LDGV4(dst, ptr)                                                     \
  asm volatile("ld.global.nc.v4.f32 {%0,%1,%2,%3}, [%4];"                   \
               : "=f"(dst.x), "=f"(dst.y), "=f"(dst.z), "=f"(dst.w)         \
               : "l"(ptr))
#define LDGF(dst, ptr) \
  asm volatile("ld.global.nc.f32 %0, [%1];" : "=f"(dst) : "l"(ptr))

#define CPASYNC16(smem_u32, gptr)                                           \
  asm volatile("cp.async.cg.shared.global [%0], [%1], 16;" ::"r"(smem_u32), \
               "l"(gptr))
#define COMMIT() asm volatile("cp.async.commit_group;" ::: "memory")
#define WAITG(n) asm volatile("cp.async.wait_group %0;" ::"n"(n) : "memory")

// ---------------------------------------------------------------------------
// P1: k = emb @ Wk.T, v = emb @ Wv.T.   (unchanged — protected win)
// ---------------------------------------------------------------------------
__global__ void __launch_bounds__(128) precompute_kv(
    const float* __restrict__ emb, const float* __restrict__ Wk,
    const float* __restrict__ Wv) {
  int gw = (blockIdx.x * 128 + threadIdx.x) >> 5;  // 0..4095
  int lane = threadIdx.x & 31;
  int sel = gw >> 11;
  int rem = gw & 2047;
  int j = rem >> 1;
  int bh = (rem & 1) * 4;
  const float* W = sel ? Wv : Wk;
  float* dst = sel ? g_v : g_k;
  const float4* w4 = reinterpret_cast<const float4*>(W + j * C);
  const float4* e4 = reinterpret_cast<const float4*>(emb);

  float4 wv[8];
#pragma unroll
  for (int i = 0; i < 8; i++) LDGV4(wv[i], w4 + lane + 32 * i);

  float acc[4];
#pragma unroll
  for (int b = 0; b < 4; b++) acc[b] = 0.f;
#pragma unroll
  for (int b = 0; b < 4; b++) {
    float4 e[8];
#pragma unroll
    for (int i = 0; i < 8; i++) e[i] = e4[(bh + b) * 256 + lane + 32 * i];
#pragma unroll
    for (int i = 0; i < 8; i++)
      acc[b] += wv[i].x * e[i].x + wv[i].y * e[i].y + wv[i].z * e[i].z +
                wv[i].w * e[i].w;
  }
#pragma unroll
  for (int b = 0; b < 4; b++)
    for (int s = 16; s; s >>= 1) acc[b] += __shfl_xor_sync(0xffffffffu, acc[b], s);
  if (lane == 0) {
#pragma unroll
    for (int b = 0; b < 4; b++) dst[(bh + b) * C + j] = acc[b];
  }
}

// ---------------------------------------------------------------------------
// P2: u/M fold.  grid (4,16,2): batch-group of 4 -> Wq/Wp read only 2x.
// ---------------------------------------------------------------------------
__global__ void __launch_bounds__(256) precompute_uM(
    const float* __restrict__ Wq, const float* __restrict__ Wp) {
  __shared__ float kk[4][D];
  __shared__ float vv[4][D];
  int h = blockIdx.y;
  int bg = blockIdx.z * 4;
  int c = blockIdx.x * 256 + threadIdx.x;
  {
    int b = threadIdx.x >> 6, d = threadIdx.x & 63;
    kk[b][d] = g_k[(bg + b) * C + h * D + d];
    vv[b][d] = g_v[(bg + b) * C + h * D + d];
  }
  __syncthreads();

  float acc[4];
#pragma unroll
  for (int b = 0; b < 4; b++) acc[b] = 0.f;
#pragma unroll
  for (int d0 = 0; d0 < D; d0 += 16) {
    float wq[16];
#pragma unroll
    for (int jj = 0; jj < 16; jj++) LDGF(wq[jj], Wq + (h * D + d0 + jj) * C + c);
#pragma unroll
    for (int jj = 0; jj < 16; jj++)
#pragma unroll
      for (int b = 0; b < 4; b++) acc[b] += wq[jj] * kk[b][d0 + jj];
  }
#pragma unroll
  for (int b = 0; b < 4; b++) g_u[((bg + b) * H + h) * C + c] = acc[b];

  float acc2[4];
#pragma unroll
  for (int b = 0; b < 4; b++) acc2[b] = 0.f;
  const float4* wp4 = reinterpret_cast<const float4*>(Wp + c * C + h * D);
#pragma unroll
  for (int i0 = 0; i0 < 16; i0 += 8) {
    float4 wp[8];
#pragma unroll
    for (int i = 0; i < 8; i++) LDGV4(wp[i], wp4 + i0 + i);
#pragma unroll
    for (int i = 0; i < 8; i++) {
      int d = (i0 + i) * 4;
#pragma unroll
      for (int b = 0; b < 4; b++)
        acc2[b] += wp[i].x * vv[b][d] + wp[i].y * vv[b][d + 1] +
                   wp[i].z * vv[b][d + 2] + wp[i].w * vv[b][d + 3];
    }
  }
#pragma unroll
  for (int b = 0; b < 4; b++) g_M[((bg + b) * H + h) * C + c] = acc2[b];
}

// ---------------------------------------------------------------------------
// PASS A: attn[b,n,h] = sigmoid(SCALE * fea[b,n,:] . u[b,h,:]).
// 144 blocks (18 per batch, never crossing a batch boundary), 256 threads.
// u[b] resident in smem; fea streamed through a 4-slot ring of 32rx256c
// chunks. Wait-then-issue ordering keeps 2-3 chunks always in flight with
// a single barrier per chunk.  Reduce once per 32-row tile.
// ---------------------------------------------------------------------------
#define NBLK_A 144
#define BPB 18                 // blocks per batch
#define CHSTR 260              // floats per chunk row (256 + pad)
#define CHF (32 * CHSTR)       // 8320 floats per chunk slot
#define U_FLOATS (H * C)       // 16384
#define PART_FLOATS (8 * 32 * 17)  // 4352
#define SMEM_A ((U_FLOATS + 4 * CHF + PART_FLOATS) * 4)  // 216064 B

__global__ void __launch_bounds__(256, 1) attn_pass(
    const float* __restrict__ fea) {
  extern __shared__ __align__(16) float sm[];
  float* u_s = sm;                 // [h][c]
  float* ring = sm + U_FLOATS;     // 4 x CHF
  float* part = ring + 4 * CHF;    // [w][r][17]

  const int t = threadIdx.x;
  const int w = t >> 5;
  const int l = t & 31;

  const int batch = blockIdx.x / BPB;
  const int bi = blockIdx.x % BPB;
  const int ts = batch * 128 + (bi * 128) / BPB;
  const int te = batch * 128 + ((bi + 1) * 128) / BPB;
  const int nQ = (te - ts) * 4;  // >= 28

  // chunk q: tile ts+q/4, cols (q&3)*256, ring slot q&3
#define ISSUE_Q(q)                                                          \
  {                                                                         \
    const float* srcb =                                                     \
        fea + (size_t)(ts + (q) / 4) * 32768 + ((q) & 3) * 256;             \
    float* db = ring + ((q) & 3) * CHF;                                     \
    _Pragma("unroll") for (int i = 0; i < 8; i++) {                         \
      int idx = t + 256 * i;                                                \
      int r = idx >> 6;                                                     \
      int c4 = idx & 63;                                                    \
      unsigned ds =                                                         \
          (unsigned)__cvta_generic_to_shared(db + r * CHSTR + c4 * 4);      \
      CPASYNC16(ds, srcb + r * 1024 + c4 * 4);                              \
    }                                                                       \
  }

  // Prologue: group0 = (u + chunk0), group1 = chunk1, group2 = chunk2.
  {
    const float4* gu4 = reinterpret_cast<const float4*>(g_u + batch * U_FLOATS);
#pragma unroll
    for (int i = 0; i < 16; i++) {
      int idx = t + 256 * i;
      unsigned ds = (unsigned)__cvta_generic_to_shared(u_s + idx * 4);
      CPASYNC16(ds, gu4 + idx);
    }
  }
  ISSUE_Q(0); COMMIT();
  ISSUE_Q(1); COMMIT();
  ISSUE_Q(2); COMMIT();

  ull p2[H];

  for (int q = 0; q < nQ; ++q) {
    WAITG(2);        // chunk q (and for q==0, u) landed
    __syncthreads(); // visibility + all threads past chunk q-1 compute
    if (q + 3 < nQ) { ISSUE_Q(q + 3); }
    COMMIT();        // one commit per iteration, empty near the tail

    const int ck = q & 3;
    if (ck == 0) {
#pragma unroll
      for (int h = 0; h < H; h++) p2[h] = 0ull;
    }

    // warp w owns f4-cols [w*8, w*8+8) of this 256-col chunk; lane = row.
    const float* fp = ring + ck * CHF + l * CHSTR + w * 32;  // slot == ck
    const float* up = u_s + ck * 256 + w * 32;
#pragma unroll
    for (int j = 0; j < 8; j++) {
      ulonglong2 f = *reinterpret_cast<const ulonglong2*>(fp + j * 4);
#pragma unroll
      for (int h = 0; h < H; h++) {
        ulonglong2 uu =
            *reinterpret_cast<const ulonglong2*>(up + h * C + j * 4);
        FMA2(p2[h], f.x, uu.x);
        FMA2(p2[h], f.y, uu.y);
      }
    }

    if (ck == 3) {  // tile finished: reduce + sigmoid + store
      const int tile = ts + (q >> 2);
#pragma unroll
      for (int h = 0; h < H; h++) {
        float lo, hi;
        asm("mov.b64 {%0,%1}, %2;" : "=f"(lo), "=f"(hi) : "l"(p2[h]));
        part[(w * 32 + l) * 17 + h] = lo + hi;
      }
      __syncthreads();
#pragma unroll
      for (int qq = 0; qq < 2; qq++) {
        int p = t + qq * 256;  // (r,h)
        int r = p >> 4;
        int h = p & 15;
        float s = 0.f;
#pragma unroll
        for (int ww = 0; ww < 8; ww++) s += part[(ww * 32 + r) * 17 + h];
        float a = 1.f / (1.f + __expf(-s * SCALE));
        ull ad;
        asm("mov.b64 %0, {%1,%1};" : "=l"(ad) : "f"(a));
        g_attnd[(tile * 32 + r) * H + h] = ad;
      }
    }
  }
}

// ---------------------------------------------------------------------------
// PASS B: out = fea + bp + attn @ M.  Pure stream, no phase coupling.
// 512 blocks x 256 thr; block = 64 rows; thread = 4 columns.
// attn (pre-duplicated f32x2) staged in 8KB smem; M[b] slice in registers.
// ---------------------------------------------------------------------------
__global__ void __launch_bounds__(256) out_pass(
    const float* __restrict__ fea, const float* __restrict__ bp,
    float* __restrict__ out) {
  __shared__ __align__(16) ull attn_s[64 * H];  // 8KB

  const int t = threadIdx.x;
  const size_t row0 = (size_t)blockIdx.x * 64;
  const int b = (int)(row0 >> 12);
  const int c0 = t * 4;

  // stage attn for 64 rows
  {
    const ulonglong2* src =
        reinterpret_cast<const ulonglong2*>(g_attnd + row0 * H);
    ulonglong2* dst = reinterpret_cast<ulonglong2*>(attn_s);
#pragma unroll
    for (int i = 0; i < 2; i++) dst[t + 256 * i] = src[t + 256 * i];
  }

  ulonglong2 bpv = *reinterpret_cast<const ulonglong2*>(bp + c0);
  ulonglong2 M2[H];
#pragma unroll
  for (int h = 0; h < H; h++)
    M2[h] = *reinterpret_cast<const ulonglong2*>(g_M + (b * H + h) * C + c0);
  __syncthreads();

  const float* fb = fea + row0 * C + c0;
  float* ob = out + row0 * C + c0;

  ulonglong2 pf0 = *reinterpret_cast<const ulonglong2*>(fb);
  ulonglong2 pf1 = *reinterpret_cast<const ulonglong2*>(fb + C);
#pragma unroll 2
  for (int r = 0; r < 64; r += 2) {
    ulonglong2 f0 = pf0, f1 = pf1;
    if (r + 2 < 64) {
      pf0 = *reinterpret_cast<const ulonglong2*>(fb + (r + 2) * C);
      pf1 = *reinterpret_cast<const ulonglong2*>(fb + (r + 3) * C);
    }
#pragma unroll
    for (int rr = 0; rr < 2; rr++) {
      ulonglong2 f = rr ? f1 : f0;
      ull oa, oc;
      ADD2(oa, f.x, bpv.x);
      ADD2(oc, f.y, bpv.y);
      const ull* ar = attn_s + (r + rr) * H;
#pragma unroll
      for (int hg = 0; hg < 8; hg++) {
        ulonglong2 a2 = *reinterpret_cast<const ulonglong2*>(ar + hg * 2);
        FMA2(oa, a2.x, M2[hg * 2].x);
        FMA2(oc, a2.x, M2[hg * 2].y);
        FMA2(oa, a2.y, M2[hg * 2 + 1].x);
        FMA2(oc, a2.y, M2[hg * 2 + 1].y);
      }
      ulonglong2 o;
      o.x = oa;
      o.y = oc;
      *reinterpret_cast<ulonglong2*>(ob + (r + rr) * C) = o;
    }
  }
}

// ---------------------------------------------------------------------------
extern "C" void kernel_launch(void* const* d_in, const int* in_sizes, int n_in,
                              void* d_out, int out_size) {
  const float* fea = (const float*)d_in[0];
  const float* emb = (const float*)d_in[1];
  const float* Wq  = (const float*)d_in[2];
  const float* Wk  = (const float*)d_in[3];
  const float* Wv  = (const float*)d_in[4];
  const float* Wp  = (const float*)d_in[5];
  const float* bp  = (const float*)d_in[6];
  float* out = (float*)d_out;

  cudaFuncSetAttribute(attn_pass, cudaFuncAttributeMaxDynamicSharedMemorySize,
                       SMEM_A);

  precompute_kv<<<1024, 128>>>(emb, Wk, Wv);
  precompute_uM<<<dim3(4, H, 2), 256>>>(Wq, Wp);
  attn_pass<<<NBLK_A, 256, SMEM_A>>>(fea);
  out_pass<<<512, 256>>>(fea, bp, out);
}